// round 2
// baseline (speedup 1.0000x reference)
#include <cuda_runtime.h>
#include <cstdint>
#include <cstddef>

#define SEQ   512
#define BATCH 64
#define INDIM 128
#define HID   512
#define NCTA  128      // 4 b-groups x 32 j-blocks
#define GROUP_CTAS 32  // CTAs per b-group barrier

// ---------------------------------------------------------------------------
// Barrier state: one {count, gen} pair per b-group. gen grows monotonically
// across launches (sampled at kernel entry -> deterministic graph replays);
// count always returns to 0 by the end of every barrier.
// ---------------------------------------------------------------------------
__device__ unsigned g_count[4];
__device__ unsigned g_gen[4];

// ---------------------------------------------------------------------------
// Kernel 1: xi[r][j] = sum_i x[r][i] * Wi[j][i] + bi[j],  r = s*BATCH+b
// 32768 rows x 512 cols, K=128. CTA tile 64x64, 256 threads, thread tile 4x4,
// K processed in 2 chunks of 64 (32KB smem -> good occupancy).
// Output written directly into d_out's h_seq region.
// ---------------------------------------------------------------------------
__global__ void __launch_bounds__(256) xi_kernel(
    const float* __restrict__ x, const float* __restrict__ Wi,
    const float* __restrict__ bi, float* __restrict__ out)
{
    extern __shared__ float sm[];
    float* xs = sm;          // [64 k][64 r]
    float* ws = sm + 4096;   // [64 k][64 j]

    const int tid = threadIdx.x;
    const int rb = blockIdx.x >> 3;   // 512 row blocks
    const int cb = blockIdx.x & 7;    // 8 col blocks
    const int r0 = rb * 64;
    const int j0 = cb * 64;

    const int rg = tid >> 4;   // 0..15
    const int jg = tid & 15;   // 0..15

    float acc[4][4];
    #pragma unroll
    for (int a = 0; a < 4; a++)
        #pragma unroll
        for (int c = 0; c < 4; c++) acc[a][c] = 0.0f;

    for (int kc = 0; kc < 2; kc++) {
        // Load chunk: 64 rows x 64 k each for x and Wi.
        // u -> r = u&63 (lane-contiguous -> conflict-free STS), k4 = u>>6.
        #pragma unroll
        for (int m = 0; m < 4; m++) {
            int u  = tid + m * 256;        // 0..1023
            int r  = u & 63;
            int k4 = u >> 6;               // 0..15
            int kg = kc * 16 + k4;         // global float4 index along K
            float4 v = *reinterpret_cast<const float4*>(
                x + (size_t)(r0 + r) * INDIM + kg * 4);
            xs[(k4 * 4 + 0) * 64 + r] = v.x;
            xs[(k4 * 4 + 1) * 64 + r] = v.y;
            xs[(k4 * 4 + 2) * 64 + r] = v.z;
            xs[(k4 * 4 + 3) * 64 + r] = v.w;
        }
        #pragma unroll
        for (int m = 0; m < 4; m++) {
            int u  = tid + m * 256;
            int j  = u & 63;
            int k4 = u >> 6;
            int kg = kc * 16 + k4;
            float4 v = *reinterpret_cast<const float4*>(
                Wi + (size_t)(j0 + j) * INDIM + kg * 4);
            ws[(k4 * 4 + 0) * 64 + j] = v.x;
            ws[(k4 * 4 + 1) * 64 + j] = v.y;
            ws[(k4 * 4 + 2) * 64 + j] = v.z;
            ws[(k4 * 4 + 3) * 64 + j] = v.w;
        }
        __syncthreads();

        #pragma unroll 8
        for (int k = 0; k < 64; k++) {
            float4 av = *reinterpret_cast<const float4*>(xs + k * 64 + rg * 4);
            float4 bv = *reinterpret_cast<const float4*>(ws + k * 64 + jg * 4);
            float aa[4] = {av.x, av.y, av.z, av.w};
            float bb[4] = {bv.x, bv.y, bv.z, bv.w};
            #pragma unroll
            for (int a = 0; a < 4; a++)
                #pragma unroll
                for (int c = 0; c < 4; c++) acc[a][c] += aa[a] * bb[c];
        }
        __syncthreads();
    }

    float4 biasv = *reinterpret_cast<const float4*>(bi + j0 + jg * 4);
    float bb4[4] = {biasv.x, biasv.y, biasv.z, biasv.w};
    #pragma unroll
    for (int a = 0; a < 4; a++) {
        float4 o;
        o.x = acc[a][0] + bb4[0];
        o.y = acc[a][1] + bb4[1];
        o.z = acc[a][2] + bb4[2];
        o.w = acc[a][3] + bb4[3];
        *reinterpret_cast<float4*>(
            out + (size_t)(r0 + rg * 4 + a) * HID + j0 + jg * 4) = o;
    }
}

// ---------------------------------------------------------------------------
// Per-b-group barrier (32 CTAs). target = gen0 + t.
// ---------------------------------------------------------------------------
__device__ __forceinline__ void group_barrier(int bg, unsigned target)
{
    __syncthreads();                         // all threads' STGs in program order
    if (threadIdx.x == 0) {
        __threadfence();                     // cumulative release (gpu scope)
        unsigned c = atomicAdd(&g_count[bg], 1u);
        if (c == GROUP_CTAS - 1u) {
            atomicExch(&g_count[bg], 0u);    // reset before gen release
            __threadfence();
            atomicAdd(&g_gen[bg], 1u);
        }
        while ((int)(*(volatile unsigned*)&g_gen[bg] - target) < 0) { }
        __threadfence();                     // acquire
    }
    __syncthreads();
}

// ---------------------------------------------------------------------------
// Kernel 2: persistent recurrence. 128 CTAs x 256 threads, one wave.
// CTA (bg, jb): bg = blockIdx.x>>5 (batch group of 16), jb = blockIdx.x&31
// (16 hidden cols). Wh tile [512k][16j] persists in smem.
// ---------------------------------------------------------------------------
__global__ void __launch_bounds__(256) rec_kernel(
    float* __restrict__ out, const float* __restrict__ Wh,
    const float* __restrict__ bh)
{
    extern __shared__ float sm[];
    float* ws  = sm;            // [512 k][16 j]   8192 floats
    float* hs  = sm + 8192;     // [512 k][16 b]   8192 floats
    float* red = sm + 16384;    // [8 w][16 b][16 j] 2048 floats

    const int tid = threadIdx.x;
    const int bg  = blockIdx.x >> 5;   // 0..3
    const int jb  = blockIdx.x & 31;   // 0..31
    const int b0  = bg * 16;
    const int j0  = jb * 16;

    // Barrier baseline (read before any arrival in this group can bump gen).
    unsigned gen0 = 0;
    if (tid == 0) gen0 = atomicAdd(&g_gen[bg], 0u);

    // Epilogue-ownership mapping: thread -> (b_e, j_e), b_e*16+j_e == tid.
    const int b_e = tid >> 4;
    const int j_e = tid & 15;
    const float bh_reg = bh[j0 + j_e];

    // --- Prologue: load Wh tile, transposed to [k][j] ---
    #pragma unroll
    for (int m = 0; m < 8; m++) {
        int u  = tid + m * 256;      // 0..2047
        int j  = u & 15;
        int k4 = u >> 4;             // 0..127
        float4 v = *reinterpret_cast<const float4*>(
            Wh + (size_t)(j0 + j) * HID + k4 * 4);
        ws[(k4 * 4 + 0) * 16 + j] = v.x;
        ws[(k4 * 4 + 1) * 16 + j] = v.y;
        ws[(k4 * 4 + 2) * 16 + j] = v.z;
        ws[(k4 * 4 + 3) * 16 + j] = v.w;
    }
    __syncthreads();

    // --- Step 0: h_0 = tanh(xi_0 + bh) (h_{-1} = 0) ---
    {
        size_t idx = (size_t)(b0 + b_e) * HID + j0 + j_e;
        out[idx] = tanhf(out[idx] + bh_reg);
    }

    // Compute-phase mapping.
    const int w    = tid >> 5;        // warp 0..7, K slice [w*64, w*64+64)
    const int lane = tid & 31;
    const int bq   = lane >> 3;       // 0..3  -> b rows bq*4..bq*4+3
    const int jq   = lane & 7;        // 0..7  -> j cols jq*2..jq*2+1
    const int kbeg = w * 64;

    // h-load mapping: thread -> row b_l = tid&15, k4 slice k4base = tid>>4.
    const int b_l     = tid & 15;
    const int k4base  = tid >> 4;     // 0..15

    for (int t = 1; t < SEQ; t++) {
        group_barrier(bg, gen0 + (unsigned)t);

        // --- Load h_{t-1} tile [16 b][512 k] -> hs [k][b] ---
        const float* hp = out + (size_t)(t - 1) * (BATCH * HID)
                              + (size_t)(b0 + b_l) * HID;
        float4 v[8];
        #pragma unroll
        for (int m = 0; m < 8; m++)
            v[m] = *reinterpret_cast<const float4*>(hp + (k4base + m * 16) * 4);
        #pragma unroll
        for (int m = 0; m < 8; m++) {
            int k = (k4base + m * 16) * 4;
            hs[(k + 0) * 16 + b_l] = v[m].x;
            hs[(k + 1) * 16 + b_l] = v[m].y;
            hs[(k + 2) * 16 + b_l] = v[m].z;
            hs[(k + 3) * 16 + b_l] = v[m].w;
        }
        __syncthreads();

        // --- Compute partial tile: 4b x 2j over 64 k ---
        float acc[4][2];
        #pragma unroll
        for (int a = 0; a < 4; a++) { acc[a][0] = 0.0f; acc[a][1] = 0.0f; }

        #pragma unroll 4
        for (int kk = 0; kk < 64; kk++) {
            int k = kbeg + kk;
            float4 a4 = *reinterpret_cast<const float4*>(hs + k * 16 + bq * 4);
            float2 b2 = *reinterpret_cast<const float2*>(ws + k * 16 + jq * 2);
            acc[0][0] += a4.x * b2.x;  acc[0][1] += a4.x * b2.y;
            acc[1][0] += a4.y * b2.x;  acc[1][1] += a4.y * b2.y;
            acc[2][0] += a4.z * b2.x;  acc[2][1] += a4.z * b2.y;
            acc[3][0] += a4.w * b2.x;  acc[3][1] += a4.w * b2.y;
        }

        // --- Cross-warp reduction via smem ---
        float2* red2 = reinterpret_cast<float2*>(red);
        #pragma unroll
        for (int a = 0; a < 4; a++) {
            float2 p; p.x = acc[a][0]; p.y = acc[a][1];
            red2[w * 128 + (bq * 4 + a) * 8 + jq] = p;
        }
        __syncthreads();

        float s = 0.0f;
        #pragma unroll
        for (int ww = 0; ww < 8; ww++) s += red[ww * 256 + tid];

        // --- Epilogue: h_t = tanh(s + bh + xi_t), overwrite xi_t in-place ---
        size_t idx = (size_t)t * (BATCH * HID)
                   + (size_t)(b0 + b_e) * HID + j0 + j_e;
        float h = tanhf(s + bh_reg + out[idx]);
        out[idx] = h;
        if (t == SEQ - 1) {
            out[(size_t)SEQ * (BATCH * HID)
                + (size_t)(b0 + b_e) * HID + j0 + j_e] = h;
        }
        __syncthreads();   // red reuse / hs overwrite safety before next barrier
    }
}

// ---------------------------------------------------------------------------
extern "C" void kernel_launch(void* const* d_in, const int* in_sizes, int n_in,
                              void* d_out, int out_size)
{
    const float* x  = (const float*)d_in[0];
    const float* Wi = (const float*)d_in[1];
    const float* bi = (const float*)d_in[2];
    const float* Wh = (const float*)d_in[3];
    const float* bh = (const float*)d_in[4];
    float* out = (float*)d_out;

    static bool attr_done = false;
    if (!attr_done) {
        cudaFuncSetAttribute(xi_kernel,
            cudaFuncAttributeMaxDynamicSharedMemorySize, 32768);
        cudaFuncSetAttribute(rec_kernel,
            cudaFuncAttributeMaxDynamicSharedMemorySize, 73728);
        attr_done = true;
    }

    xi_kernel<<<4096, 256, 32768>>>(x, Wi, bi, out);
    rec_kernel<<<NCTA, 256, 73728>>>(out, Wh, bh);
}

// round 3
// speedup vs baseline: 1.4135x; 1.4135x over previous
#include <cuda_runtime.h>
#include <cstdint>
#include <cstddef>

#define SEQ   512
#define BATCH 64
#define INDIM 128
#define HID   512
#define BH    (BATCH * HID)   // 32768 floats per timestep slice

// ---------------------------------------------------------------------------
// Kernel 1: xi[r][j] = sum_i x[r][i] * Wi[j][i] + bi[j],  r = s*BATCH+b
// 32768 rows x 512 cols, K=128. CTA tile 64x64, 256 threads, thread tile 4x4.
// Output written directly into d_out's h_seq region (overwritten by h later).
// ---------------------------------------------------------------------------
__global__ void __launch_bounds__(256) xi_kernel(
    const float* __restrict__ x, const float* __restrict__ Wi,
    const float* __restrict__ bi, float* __restrict__ out)
{
    __shared__ alignas(16) float xs[4096];   // [64 k][64 r]
    __shared__ alignas(16) float ws[4096];   // [64 k][64 j]

    const int tid = threadIdx.x;
    const int rb = blockIdx.x >> 3;
    const int cb = blockIdx.x & 7;
    const int r0 = rb * 64;
    const int j0 = cb * 64;

    const int rg = tid >> 4;
    const int jg = tid & 15;

    float acc[4][4];
    #pragma unroll
    for (int a = 0; a < 4; a++)
        #pragma unroll
        for (int c = 0; c < 4; c++) acc[a][c] = 0.0f;

    for (int kc = 0; kc < 2; kc++) {
        #pragma unroll
        for (int m = 0; m < 4; m++) {
            int u  = tid + m * 256;
            int r  = u & 63;
            int k4 = u >> 6;
            int kg = kc * 16 + k4;
            float4 v = *reinterpret_cast<const float4*>(
                x + (size_t)(r0 + r) * INDIM + kg * 4);
            xs[(k4 * 4 + 0) * 64 + r] = v.x;
            xs[(k4 * 4 + 1) * 64 + r] = v.y;
            xs[(k4 * 4 + 2) * 64 + r] = v.z;
            xs[(k4 * 4 + 3) * 64 + r] = v.w;
        }
        #pragma unroll
        for (int m = 0; m < 4; m++) {
            int u  = tid + m * 256;
            int j  = u & 63;
            int k4 = u >> 6;
            int kg = kc * 16 + k4;
            float4 v = *reinterpret_cast<const float4*>(
                Wi + (size_t)(j0 + j) * INDIM + kg * 4);
            ws[(k4 * 4 + 0) * 64 + j] = v.x;
            ws[(k4 * 4 + 1) * 64 + j] = v.y;
            ws[(k4 * 4 + 2) * 64 + j] = v.z;
            ws[(k4 * 4 + 3) * 64 + j] = v.w;
        }
        __syncthreads();

        #pragma unroll 8
        for (int k = 0; k < 64; k++) {
            float4 av = *reinterpret_cast<const float4*>(xs + k * 64 + rg * 4);
            float4 bv = *reinterpret_cast<const float4*>(ws + k * 64 + jg * 4);
            float aa[4] = {av.x, av.y, av.z, av.w};
            float bb[4] = {bv.x, bv.y, bv.z, bv.w};
            #pragma unroll
            for (int a = 0; a < 4; a++)
                #pragma unroll
                for (int c = 0; c < 4; c++) acc[a][c] += aa[a] * bb[c];
        }
        __syncthreads();
    }

    float4 biasv = *reinterpret_cast<const float4*>(bi + j0 + jg * 4);
    float bb4[4] = {biasv.x, biasv.y, biasv.z, biasv.w};
    #pragma unroll
    for (int a = 0; a < 4; a++) {
        float4 o;
        o.x = acc[a][0] + bb4[0];
        o.y = acc[a][1] + bb4[1];
        o.z = acc[a][2] + bb4[2];
        o.w = acc[a][3] + bb4[3];
        *reinterpret_cast<float4*>(
            out + (size_t)(r0 + rg * 4 + a) * HID + j0 + jg * 4) = o;
    }
}

// ---------------------------------------------------------------------------
// Kernel 2: persistent recurrence, cluster-synchronized.
// 16 clusters x 8 CTAs. Cluster = batch group of 4 (b0 = (blockIdx.x>>3)*4).
// CTA j-slice: j0 = (blockIdx.x&7)*64.
// Per CTA: output tile 4b x 64j, K = 512.
// Wh lives entirely in REGISTERS: warp (jh, ks) covers j-half jh*32 and
// K-slice ks*128; each thread owns one j and 128 Wh values.
// Per step: cluster.sync -> load h[4][512] (8KB, L2) into smem [k][4b]
// -> outer-product compute (broadcast LDS.128 + 4 FFMA per k)
// -> smem reduce over 4 K-slices -> tanh epilogue over prefetched xi -> STG.
// One cluster barrier per step; barrier.cluster arrive(release)/wait(acquire)
// orders the gmem h stores for cluster peers.
// ---------------------------------------------------------------------------
__global__ void __launch_bounds__(256) __cluster_dims__(8, 1, 1)
rec_kernel(float* __restrict__ out, const float* __restrict__ Wh,
           const float* __restrict__ bh)
{
    __shared__ alignas(16) float hs[2048];    // [512 k][4 b]
    __shared__ alignas(16) float red[1024];   // [4 ks][4 b][64 j]

    const int tid = threadIdx.x;
    const int b0  = (blockIdx.x >> 3) * 4;    // batch group base
    const int j0  = (blockIdx.x & 7) * 64;    // hidden slice base

    // Compute mapping
    const int w    = tid >> 5;        // warp 0..7
    const int jh   = w & 1;           // j half
    const int ks   = w >> 1;          // K slice 0..3
    const int lane = tid & 31;
    const int jj   = jh * 32 + lane;  // 0..63 within CTA j-slice
    const int k0   = ks * 128;

    // Epilogue mapping: one output element per thread
    const int be = tid >> 6;          // 0..3
    const int je = tid & 63;          // 0..63
    const float bh_e = bh[j0 + je];

    // --- Prologue: Wh slice into registers (constant across all steps) ---
    float wreg[128];
    {
        const float4* wp = reinterpret_cast<const float4*>(
            Wh + (size_t)(j0 + jj) * HID + k0);
        #pragma unroll
        for (int i = 0; i < 32; i++) {
            float4 v = wp[i];
            wreg[i * 4 + 0] = v.x;
            wreg[i * 4 + 1] = v.y;
            wreg[i * 4 + 2] = v.z;
            wreg[i * 4 + 3] = v.w;
        }
    }

    // --- Step 0: h_0 = tanh(xi_0 + bh), h_{-1} = 0 ---
    {
        size_t idx = (size_t)(b0 + be) * HID + j0 + je;
        out[idx] = tanhf(out[idx] + bh_e);
    }

    // h-load mapping: thread handles k = tid and k = tid + 256
    for (int t = 1; t < SEQ; t++) {
        // Prefetch xi_t (independent of h; issued before the barrier)
        size_t oidx = (size_t)t * BH + (size_t)(b0 + be) * HID + j0 + je;
        float xf = out[oidx];

        // Cluster barrier: all peers' h_{t-1} stores become visible.
        asm volatile("barrier.cluster.arrive.aligned;" ::: "memory");
        asm volatile("barrier.cluster.wait.aligned;"   ::: "memory");

        // --- Load h_{t-1}[4][512] -> hs[k][4b] (transposed gather) ---
        const float* prev = out + (size_t)(t - 1) * BH + (size_t)b0 * HID;
        #pragma unroll
        for (int m = 0; m < 2; m++) {
            int k = tid + m * 256;
            float4 v;
            v.x = prev[0 * HID + k];
            v.y = prev[1 * HID + k];
            v.z = prev[2 * HID + k];
            v.w = prev[3 * HID + k];
            *reinterpret_cast<float4*>(hs + k * 4) = v;
        }
        __syncthreads();

        // --- Compute: acc[b] = sum_{k in slice} Wh[j][k] * h[b][k] ---
        float acc0 = 0.f, acc1 = 0.f, acc2 = 0.f, acc3 = 0.f;
        const float* hp = hs + k0 * 4;
        #pragma unroll
        for (int i = 0; i < 128; i++) {
            float4 hb = *reinterpret_cast<const float4*>(hp + i * 4);
            float wv = wreg[i];
            acc0 += wv * hb.x;
            acc1 += wv * hb.y;
            acc2 += wv * hb.z;
            acc3 += wv * hb.w;
        }

        // --- Reduce across 4 K-slices via smem ---
        red[ks * 256 + 0 * 64 + jj] = acc0;
        red[ks * 256 + 1 * 64 + jj] = acc1;
        red[ks * 256 + 2 * 64 + jj] = acc2;
        red[ks * 256 + 3 * 64 + jj] = acc3;
        __syncthreads();

        float s = red[0 * 256 + be * 64 + je]
                + red[1 * 256 + be * 64 + je]
                + red[2 * 256 + be * 64 + je]
                + red[3 * 256 + be * 64 + je];

        // --- Epilogue: h_t = tanh(s + bh + xi_t), overwrite xi_t ---
        float h = tanhf(s + bh_e + xf);
        out[oidx] = h;
        if (t == SEQ - 1) {
            out[(size_t)SEQ * BH + (size_t)(b0 + be) * HID + j0 + je] = h;
        }
        // Next iteration's cluster barrier doubles as the intra-CTA barrier
        // protecting red/hs reuse (every thread participates).
    }
}

// ---------------------------------------------------------------------------
extern "C" void kernel_launch(void* const* d_in, const int* in_sizes, int n_in,
                              void* d_out, int out_size)
{
    const float* x  = (const float*)d_in[0];
    const float* Wi = (const float*)d_in[1];
    const float* bi = (const float*)d_in[2];
    const float* Wh = (const float*)d_in[3];
    const float* bh = (const float*)d_in[4];
    float* out = (float*)d_out;

    xi_kernel<<<4096, 256>>>(x, Wi, bi, out);
    rec_kernel<<<128, 256>>>(out, Wh, bh);
}